// round 13
// baseline (speedup 1.0000x reference)
#include <cuda_runtime.h>
#include <cstdint>

// Moment feature expansion, order 4, latent dim 16.
// out[b,t,:] = [1, x(16), f2(136), f3(816), f4(3876)] -> 4845 channels.
// Round 13: R12 (interior/boundary split of f4 quads) with corrected table
// capacities (interior count > 512 per phase; arrays now sized for the full
// 969-quad worst case). Interior quad: one k -> scalar f3 LDS.32 + one
// LDS.128 from 4-phase-replicated x. Boundary quad: R10 pairwise path.

#define D    16
#define N2   136
#define N3   816
#define N4   3876
#define NOUT 4845
#define NTHREADS 256

#define F2S 137      // floats per f2 copy; copy1 base 548 B == 4 (mod 8)
#define F3S 817      // floats per f3 copy; copy1 base 3268 B == 4 (mod 8)
#define XS  17       // floats per x  copy; copy1 base 68 B == 4 (mod 8)
#define XQS 23       // floats per x quad-copy; 92 B == 12 (mod 16)

#define MAXQ 976     // >= 969, multiple of 4 (16B-aligned table rows)

struct Tab2 { uint16_t v[N2]; };
struct Tab4 { uint16_t v[N4]; };
struct Tp3  { uint32_t v[2][408]; };        // [row-parity phase][pair]
struct F4Tabs {
    uint32_t intw[4][MAXQ];      // interior: g[31:22]|xqoff[21:13]|f3off[12:0]
    uint32_t bndw[4][2 * MAXQ];  // boundary pairs; word0 carries g at [23:14]
    int nint[4];
    int nbnd[4];
};

constexpr Tab2 gen2() {
    Tab2 t{}; int m = 0;
    for (int k = 0; k < D; k++)
        for (int j = 0; j <= k; j++)
            t.v[m++] = (uint16_t)((k << 4) | j);
    return t;
}

constexpr Tab4 gen4() {
    Tab4 t{}; int m = 0;
    int off[D] = {};
    for (int j = 0; j < D; j++) {
        int a = D + 2 - j;                       // 18 - j
        off[j] = N3 - a * (a - 1) * (a - 2) / 6;
    }
    for (int k = 0; k < N3; k++)
        for (int j = 0; j < D; j++)
            if (k >= off[j]) t.v[m++] = (uint16_t)((k << 4) | j);
    return t;
}

// Order-3 pair word: [10:0]=f2 byte off (incl parity copy), [11]=reset flag,
// [31:24]=x byte off (incl parity copy).
constexpr Tp3 genP3() {
    Tp3 t{};
    int off[D] = {};
    for (int j = 0; j < D; j++)
        off[j] = N2 - (D - j) * (D - j + 1) / 2;
    uint16_t kk[N3] = {}, jj[N3] = {};
    int m = 0;
    for (int k = 0; k < N2; k++)
        for (int j = 0; j < D; j++)
            if (k >= off[j]) { kk[m] = (uint16_t)k; jj[m] = (uint16_t)j; m++; }
    for (int h = 0; h < 2; h++) {
        int np = (N3 - h) / 2;                   // 408 or 407
        for (int p = 0; p < np; p++) {
            int a = h + 2 * p, b = a + 1;
            uint32_t k2 = kk[a], j = jj[a];
            uint32_t o2 = (k2 & 1u) * (F2S * 4u) + 4u * k2;
            uint32_t ox = (j & 1u) * (XS * 4u) + 4u * j;
            uint32_t fl = (kk[b] != k2) ? 1u : 0u;
            t.v[h][p] = o2 | (fl << 11) | (ox << 24);
        }
    }
    return t;
}

// f4 tables: interior quads (one k) vs boundary quads (pairwise).
constexpr F4Tabs genF4() {
    F4Tabs t{};
    int off[D] = {};
    for (int j = 0; j < D; j++) {
        int a = D + 2 - j;
        off[j] = N3 - a * (a - 1) * (a - 2) / 6;
    }
    uint16_t kk[N4] = {}, jj[N4] = {};
    int m = 0;
    for (int k = 0; k < N3; k++)
        for (int j = 0; j < D; j++)
            if (k >= off[j]) { kk[m] = (uint16_t)k; jj[m] = (uint16_t)j; m++; }
    for (int h = 0; h < 4; h++) {
        int nv = (N4 - h) >> 2;
        int ni = 0, nb = 0;
        for (int g = 0; g < nv; g++) {
            int m0 = h + 4 * g;
            if (kk[m0] == kk[m0 + 3]) {
                // interior: f3[k] scalar + x[j..j+3] quad
                uint32_t f3o = 4u * kk[m0];                  // copy0, <= 3260
                uint32_t j0  = jj[m0];
                uint32_t xo  = (j0 & 3u) * (XQS * 4u) + 4u * j0; // 16B-aligned
                t.intw[h][ni++] = ((uint32_t)g << 22) | (xo << 13) | f3o;
            } else {
                for (int pr = 0; pr < 2; pr++) {
                    int a = m0 + 2 * pr, b = a + 1;
                    uint32_t ka = kk[a], ja = jj[a];
                    uint32_t o3 = (ka & 1u) * (F3S * 4u) + 4u * ka;  // 8B align
                    uint32_t ox = (ja & 1u) * (XS * 4u) + 4u * ja;   // 8B align
                    uint32_t fl = (kk[b] != (int)ka) ? 1u : 0u;
                    uint32_t w = o3 | (fl << 13) | (ox << 24);
                    if (pr == 0) w |= ((uint32_t)g << 14);
                    t.bndw[h][2 * nb + pr] = w;
                }
                nb++;
            }
        }
        t.nint[h] = ni; t.nbnd[h] = nb;
    }
    return t;
}

__device__ constexpr Tab2 c_t2 = gen2();
__device__ constexpr Tab4 c_t4 = gen4();
__device__ __align__(8)  constexpr Tp3  c_p3 = genP3();
__device__ __align__(16) constexpr F4Tabs c_f4 = genF4();

// One f4 pair: e0 = f3[k]*x[j]; e1 = reset? f3[k+1]*x0 : f3[k]*x[j+1]
__device__ __forceinline__ float2 pairv(uint32_t u,
                                        const char* __restrict__ f3b,
                                        const char* __restrict__ xb,
                                        float x0) {
    const float2 f  = *(const float2*)(f3b + (u & 0x1FFFu));
    const float2 xv = *(const float2*)(xb + (u >> 24));
    return make_float2(f.x * xv.x,
                       (u & (1u << 13)) ? f.y * x0 : f.x * xv.y);
}

__global__ __launch_bounds__(NTHREADS)
void Moment_2774548873409_kernel(const float* __restrict__ in,
                                 float* __restrict__ out,
                                 int half) {
    __shared__ __align__(16) float f3r[2][2 * F3S];
    __shared__ __align__(16) float f2r[2][2 * F2S];
    __shared__ __align__(16) float xr[2][2 * XS];
    __shared__ __align__(16) float xq[2][4 * XQS];  // 4 alignment-phase copies

    const int t = threadIdx.x;
    const int rowA = blockIdx.x;
    const int rowB = rowA + half;       // half % 4 == 0 -> same phases

    const size_t gA = (size_t)rowA * NOUT;
    const size_t gB = (size_t)rowB * NOUT;
    float* __restrict__ oA = out + gA;
    float* __restrict__ oB = out + gB;

    // --- orders 0, 1 (+ pad init), both rows ---
    if (t < D) {
        const float vA = in[(size_t)rowA * D + t];
        xr[0][t] = vA; xr[0][XS + t] = vA; oA[1 + t] = vA;
        const float vB = in[(size_t)rowB * D + t];
        xr[1][t] = vB; xr[1][XS + t] = vB; oB[1 + t] = vB;
    }
    if (t == 0) {
        oA[0] = 1.0f; oB[0] = 1.0f;
        #pragma unroll
        for (int r = 0; r < 2; r++) {
            xr[r][D] = 0.0f;   xr[r][XS + D] = 0.0f;
            f2r[r][N2] = 0.0f; f2r[r][F2S + N2] = 0.0f;
            f3r[r][N3] = 0.0f; f3r[r][F3S + N3] = 0.0f;
        }
    }
    __syncthreads();
    const float x0A = xr[0][0];
    const float x0B = xr[1][0];

    // --- order 2, both rows (272 items) + x quad-replica fill (184 items) ---
    #pragma unroll
    for (int it = t; it < 2 * N2; it += NTHREADS) {
        const int r = (it >= N2) ? 1 : 0;
        const int i = it - r * N2;
        const uint16_t p = c_t2.v[i];
        const float v = xr[r][p >> 4] * xr[r][p & 15];
        f2r[r][i] = v; f2r[r][F2S + i] = v;
        (r ? oB : oA)[17 + i] = v;
    }
    if (t < 2 * 4 * XQS) {                    // 184 threads fill xq
        const int r = (t >= 4 * XQS) ? 1 : 0;
        const int idx = t - r * 4 * XQS;
        const int i = idx % XQS;              // element within copy
        xq[r][idx] = (i < D) ? xr[r][i] : 0.0f;
    }
    __syncthreads();

    const char* __restrict__ f2bA = (const char*)&f2r[0][0];
    const char* __restrict__ f2bB = (const char*)&f2r[1][0];
    const char* __restrict__ xbA  = (const char*)&xr[0][0];
    const char* __restrict__ xbB  = (const char*)&xr[1][0];

    // --- order 3: decode once, apply to both rows ---
    const int h3 = (int)((gA + 153) & 1);
    if (h3 == 0) {
        #pragma unroll 2
        for (int p = t; p < 408; p += NTHREADS) {
            const uint32_t w  = c_p3.v[0][p];
            const uint32_t o2 = w & 0x7FFu;
            const uint32_t ox = w >> 24;
            const uint32_t fl = w & (1u << 11);
            const int m = 2 * p;
            {
                const float2 f  = *(const float2*)(f2bA + o2);
                const float2 xv = *(const float2*)(xbA + ox);
                const float e0 = f.x * xv.x;
                const float e1 = fl ? f.y * x0A : f.x * xv.y;
                *(float2*)(&f3r[0][m]) = make_float2(e0, e1);
                f3r[0][F3S + m] = e0; f3r[0][F3S + m + 1] = e1;
                *(float2*)(oA + 153 + m) = make_float2(e0, e1);
            }
            {
                const float2 f  = *(const float2*)(f2bB + o2);
                const float2 xv = *(const float2*)(xbB + ox);
                const float e0 = f.x * xv.x;
                const float e1 = fl ? f.y * x0B : f.x * xv.y;
                *(float2*)(&f3r[1][m]) = make_float2(e0, e1);
                f3r[1][F3S + m] = e0; f3r[1][F3S + m + 1] = e1;
                *(float2*)(oB + 153 + m) = make_float2(e0, e1);
            }
        }
    } else {
        #pragma unroll 2
        for (int p = t; p < 407; p += NTHREADS) {
            const uint32_t w  = c_p3.v[1][p];
            const uint32_t o2 = w & 0x7FFu;
            const uint32_t ox = w >> 24;
            const uint32_t fl = w & (1u << 11);
            const int m = 1 + 2 * p;
            {
                const float2 f  = *(const float2*)(f2bA + o2);
                const float2 xv = *(const float2*)(xbA + ox);
                const float e0 = f.x * xv.x;
                const float e1 = fl ? f.y * x0A : f.x * xv.y;
                f3r[0][m] = e0; f3r[0][m + 1] = e1;
                *(float2*)(&f3r[0][F3S + m]) = make_float2(e0, e1);
                *(float2*)(oA + 153 + m) = make_float2(e0, e1);
            }
            {
                const float2 f  = *(const float2*)(f2bB + o2);
                const float2 xv = *(const float2*)(xbB + ox);
                const float e0 = f.x * xv.x;
                const float e1 = fl ? f.y * x0B : f.x * xv.y;
                f3r[1][m] = e0; f3r[1][m + 1] = e1;
                *(float2*)(&f3r[1][F3S + m]) = make_float2(e0, e1);
                *(float2*)(oB + 153 + m) = make_float2(e0, e1);
            }
        }
        if (t == 0) {            // f3[0] = f2[0] * x0
            float v = f2r[0][0] * x0A;
            f3r[0][0] = v; f3r[0][F3S] = v; oA[153] = v;
            v = f2r[1][0] * x0B;
            f3r[1][0] = v; f3r[1][F3S] = v; oB[153] = v;
        }
        if (t == 1) {            // f3[815] = f2[135] * x[15]
            float v = f2r[0][135] * xr[0][15];
            f3r[0][815] = v; f3r[0][F3S + 815] = v; oA[153 + 815] = v;
            v = f2r[1][135] * xr[1][15];
            f3r[1][815] = v; f3r[1][F3S + 815] = v; oB[153 + 815] = v;
        }
    }
    __syncthreads();

    // --- order 4 ---
    const char* __restrict__ f3bA = (const char*)&f3r[0][0];
    const char* __restrict__ f3bB = (const char*)&f3r[1][0];
    const char* __restrict__ xqbA = (const char*)&xq[0][0];
    const char* __restrict__ xqbB = (const char*)&xq[1][0];
    float* __restrict__ o4A = oA + 969;
    float* __restrict__ o4B = oB + 969;
    const int a4 = (int)((gA + 969) & 3);
    const int hh = (4 - a4) & 3;

    if (t < hh) {
        const uint16_t p = c_t4.v[t];
        o4A[t] = f3r[0][p >> 4] * xr[0][p & 15];
        o4B[t] = f3r[1][p >> 4] * xr[1][p & 15];
    }

    float4* __restrict__ ovA = (float4*)(o4A + hh);
    float4* __restrict__ ovB = (float4*)(o4B + hh);

    // Interior quads: one k per quad -> scalar f3 + x quad.
    const int nint = c_f4.nint[hh];
    const uint32_t* __restrict__ itw = &c_f4.intw[hh][0];
    #pragma unroll 2
    for (int q = t; q < nint; q += NTHREADS) {
        const uint32_t u = itw[q];
        const int g = u >> 22;
        const uint32_t f3o = u & 0x1FFFu;
        const uint32_t xo  = (u >> 13) & 0x1FFu;
        {
            const float f = *(const float*)(f3bA + f3o);
            const float4 xv = *(const float4*)(xqbA + xo);
            ovA[g] = make_float4(f * xv.x, f * xv.y, f * xv.z, f * xv.w);
        }
        {
            const float f = *(const float*)(f3bB + f3o);
            const float4 xv = *(const float4*)(xqbB + xo);
            ovB[g] = make_float4(f * xv.x, f * xv.y, f * xv.z, f * xv.w);
        }
    }

    // Boundary quads: pairwise (R10 path), group id in word0 bits [23:14].
    const int nbnd = c_f4.nbnd[hh];
    const uint2* __restrict__ bt = (const uint2*)&c_f4.bndw[hh][0];
    #pragma unroll 2
    for (int q = t; q < nbnd; q += NTHREADS) {
        const uint2 w = bt[q];
        const int g = (w.x >> 14) & 0x3FFu;
        {
            const float2 r0 = pairv(w.x, f3bA, xbA, x0A);
            const float2 r1 = pairv(w.y, f3bA, xbA, x0A);
            ovA[g] = make_float4(r0.x, r0.y, r1.x, r1.y);
        }
        {
            const float2 r0 = pairv(w.x, f3bB, xbB, x0B);
            const float2 r1 = pairv(w.y, f3bB, xbB, x0B);
            ovB[g] = make_float4(r0.x, r0.y, r1.x, r1.y);
        }
    }

    // Tail scalars (at most 3).
    const int nv = (N4 - hh) >> 2;
    const int done = hh + 4 * nv;
    if (t < N4 - done) {
        const int m = done + t;
        const uint16_t p = c_t4.v[m];
        o4A[m] = f3r[0][p >> 4] * xr[0][p & 15];
        o4B[m] = f3r[1][p >> 4] * xr[1][p & 15];
    }
}

extern "C" void kernel_launch(void* const* d_in, const int* in_sizes, int n_in,
                              void* d_out, int out_size) {
    const float* in = (const float*)d_in[0];
    float* out = (float*)d_out;
    const int rows = in_sizes[0] / D;            // 8192
    const int half = rows >> 1;                  // 4096, % 4 == 0
    Moment_2774548873409_kernel<<<half, NTHREADS>>>(in, out, half);
}

// round 14
// speedup vs baseline: 1.4627x; 1.4627x over previous
#include <cuda_runtime.h>
#include <cstdint>

// Moment feature expansion, order 4, latent dim 16.
// out[b,t,:] = [1, x(16), f2(136), f3(816), f4(3876)] -> 4845 channels.
// Round 14: R10 (two phase-matched rows/block, pairwise order-3/4, uint2
// tables, contiguous in-order stores) + one-ahead prefetch of the f4 table
// word (double-buffered uint2, unroll 1) to take the table LDG off the
// per-iteration dependency chain. Everything else identical to R10.

#define D    16
#define N2   136
#define N3   816
#define N4   3876
#define NOUT 4845
#define NTHREADS 256

#define F2S 137      // floats per f2 copy; copy1 base 548 B == 4 (mod 8)
#define F3S 817      // floats per f3 copy; copy1 base 3268 B == 4 (mod 8)
#define XS  17       // floats per x  copy; copy1 base 68 B == 4 (mod 8)
#define MAXG 969     // max float4 groups in f4 (phase 0)

struct Tab2 { uint16_t v[N2]; };
struct Tab4 { uint16_t v[N4]; };
struct Tp3  { uint32_t v[2][408]; };        // [row-parity phase][pair]
struct Grp4 { uint32_t v[4][MAXG * 2]; };   // [gmem phase][group*2 + pair]

constexpr Tab2 gen2() {
    Tab2 t{}; int m = 0;
    for (int k = 0; k < D; k++)
        for (int j = 0; j <= k; j++)
            t.v[m++] = (uint16_t)((k << 4) | j);
    return t;
}

constexpr Tab4 gen4() {
    Tab4 t{}; int m = 0;
    int off[D] = {};
    for (int j = 0; j < D; j++) {
        int a = D + 2 - j;                       // 18 - j
        off[j] = N3 - a * (a - 1) * (a - 2) / 6;
    }
    for (int k = 0; k < N3; k++)
        for (int j = 0; j < D; j++)
            if (k >= off[j]) t.v[m++] = (uint16_t)((k << 4) | j);
    return t;
}

// Order-3 pair word: [10:0]=f2 byte off (incl parity copy), [11]=reset flag,
// [31:24]=x byte off (incl parity copy).
constexpr Tp3 genP3() {
    Tp3 t{};
    int off[D] = {};
    for (int j = 0; j < D; j++)
        off[j] = N2 - (D - j) * (D - j + 1) / 2;
    uint16_t kk[N3] = {}, jj[N3] = {};
    int m = 0;
    for (int k = 0; k < N2; k++)
        for (int j = 0; j < D; j++)
            if (k >= off[j]) { kk[m] = (uint16_t)k; jj[m] = (uint16_t)j; m++; }
    for (int h = 0; h < 2; h++) {
        int np = (N3 - h) / 2;                   // 408 or 407
        for (int p = 0; p < np; p++) {
            int a = h + 2 * p, b = a + 1;
            uint32_t k2 = kk[a], j = jj[a];
            uint32_t o2 = (k2 & 1u) * (F2S * 4u) + 4u * k2;
            uint32_t ox = (j & 1u) * (XS * 4u) + 4u * j;
            uint32_t fl = (kk[b] != k2) ? 1u : 0u;   // reset <=> !(j->j+1)
            t.v[h][p] = o2 | (fl << 11) | (ox << 24);
        }
    }
    return t;
}

// Order-4 pair word: [12:0]=f3 byte off (incl parity copy), [13]=reset flag,
// [31:24]=x byte off (incl parity copy).
constexpr Grp4 genG() {
    Grp4 t{};
    int off[D] = {};
    for (int j = 0; j < D; j++) {
        int a = D + 2 - j;
        off[j] = N3 - a * (a - 1) * (a - 2) / 6;
    }
    uint16_t kk[N4] = {}, jj[N4] = {};
    int m = 0;
    for (int k = 0; k < N3; k++)
        for (int j = 0; j < D; j++)
            if (k >= off[j]) { kk[m] = (uint16_t)k; jj[m] = (uint16_t)j; m++; }
    for (int h = 0; h < 4; h++) {
        int nv = (N4 - h) >> 2;
        for (int g = 0; g < nv; g++)
            for (int pr = 0; pr < 2; pr++) {
                int a = h + 4 * g + 2 * pr, b = a + 1;
                uint32_t ka = kk[a], ja = jj[a];
                uint32_t o3 = (ka & 1u) * (F3S * 4u) + 4u * ka;   // 8B aligned
                uint32_t ox = (ja & 1u) * (XS * 4u) + 4u * ja;    // 8B aligned
                uint32_t fl = (kk[b] != ka) ? 1u : 0u;
                t.v[h][2 * g + pr] = o3 | (fl << 13) | (ox << 24);
            }
    }
    return t;
}

__device__ constexpr Tab2 c_t2 = gen2();
__device__ constexpr Tab4 c_t4 = gen4();
__device__ __align__(8)  constexpr Tp3  c_p3 = genP3();
__device__ __align__(16) constexpr Grp4 c_g4 = genG();

// One f4 pair: e0 = f3[k]*x[j]; e1 = reset? f3[k+1]*x0 : f3[k]*x[j+1]
__device__ __forceinline__ float2 pairv(uint32_t u,
                                        const char* __restrict__ f3b,
                                        const char* __restrict__ xb,
                                        float x0) {
    const float2 f  = *(const float2*)(f3b + (u & 0x1FFFu));
    const float2 xv = *(const float2*)(xb + (u >> 24));
    return make_float2(f.x * xv.x,
                       (u & (1u << 13)) ? f.y * x0 : f.x * xv.y);
}

__global__ __launch_bounds__(NTHREADS)
void Moment_2774548873409_kernel(const float* __restrict__ in,
                                 float* __restrict__ out,
                                 int half) {
    __shared__ __align__(16) float f3r[2][2 * F3S];
    __shared__ __align__(16) float f2r[2][2 * F2S];
    __shared__ __align__(16) float xr[2][2 * XS];

    const int t = threadIdx.x;
    const int rowA = blockIdx.x;
    const int rowB = rowA + half;       // half % 4 == 0 -> same phases

    const size_t gA = (size_t)rowA * NOUT;
    const size_t gB = (size_t)rowB * NOUT;
    float* __restrict__ oA = out + gA;
    float* __restrict__ oB = out + gB;

    // --- orders 0, 1 (+ pad init), both rows ---
    if (t < D) {
        const float vA = in[(size_t)rowA * D + t];
        xr[0][t] = vA; xr[0][XS + t] = vA; oA[1 + t] = vA;
        const float vB = in[(size_t)rowB * D + t];
        xr[1][t] = vB; xr[1][XS + t] = vB; oB[1 + t] = vB;
    }
    if (t == 0) {
        oA[0] = 1.0f; oB[0] = 1.0f;
        #pragma unroll
        for (int r = 0; r < 2; r++) {
            xr[r][D] = 0.0f;   xr[r][XS + D] = 0.0f;
            f2r[r][N2] = 0.0f; f2r[r][F2S + N2] = 0.0f;
            f3r[r][N3] = 0.0f; f3r[r][F3S + N3] = 0.0f;
        }
    }
    __syncthreads();
    const float x0A = xr[0][0];
    const float x0B = xr[1][0];

    // --- order 2, both rows: 272 work items, strided ---
    #pragma unroll
    for (int it = t; it < 2 * N2; it += NTHREADS) {
        const int r = (it >= N2) ? 1 : 0;
        const int i = it - r * N2;
        const uint16_t p = c_t2.v[i];
        const float v = xr[r][p >> 4] * xr[r][p & 15];
        f2r[r][i] = v; f2r[r][F2S + i] = v;
        (r ? oB : oA)[17 + i] = v;
    }
    __syncthreads();

    const char* __restrict__ f2bA = (const char*)&f2r[0][0];
    const char* __restrict__ f2bB = (const char*)&f2r[1][0];
    const char* __restrict__ xbA  = (const char*)&xr[0][0];
    const char* __restrict__ xbB  = (const char*)&xr[1][0];

    // --- order 3: decode once, apply to both rows ---
    const int h3 = (int)((gA + 153) & 1);
    if (h3 == 0) {
        #pragma unroll 2
        for (int p = t; p < 408; p += NTHREADS) {
            const uint32_t w  = c_p3.v[0][p];
            const uint32_t o2 = w & 0x7FFu;
            const uint32_t ox = w >> 24;
            const uint32_t fl = w & (1u << 11);
            const int m = 2 * p;
            {
                const float2 f  = *(const float2*)(f2bA + o2);
                const float2 xv = *(const float2*)(xbA + ox);
                const float e0 = f.x * xv.x;
                const float e1 = fl ? f.y * x0A : f.x * xv.y;
                *(float2*)(&f3r[0][m]) = make_float2(e0, e1);
                f3r[0][F3S + m] = e0; f3r[0][F3S + m + 1] = e1;
                *(float2*)(oA + 153 + m) = make_float2(e0, e1);
            }
            {
                const float2 f  = *(const float2*)(f2bB + o2);
                const float2 xv = *(const float2*)(xbB + ox);
                const float e0 = f.x * xv.x;
                const float e1 = fl ? f.y * x0B : f.x * xv.y;
                *(float2*)(&f3r[1][m]) = make_float2(e0, e1);
                f3r[1][F3S + m] = e0; f3r[1][F3S + m + 1] = e1;
                *(float2*)(oB + 153 + m) = make_float2(e0, e1);
            }
        }
    } else {
        #pragma unroll 2
        for (int p = t; p < 407; p += NTHREADS) {
            const uint32_t w  = c_p3.v[1][p];
            const uint32_t o2 = w & 0x7FFu;
            const uint32_t ox = w >> 24;
            const uint32_t fl = w & (1u << 11);
            const int m = 1 + 2 * p;
            {
                const float2 f  = *(const float2*)(f2bA + o2);
                const float2 xv = *(const float2*)(xbA + ox);
                const float e0 = f.x * xv.x;
                const float e1 = fl ? f.y * x0A : f.x * xv.y;
                f3r[0][m] = e0; f3r[0][m + 1] = e1;
                *(float2*)(&f3r[0][F3S + m]) = make_float2(e0, e1);
                *(float2*)(oA + 153 + m) = make_float2(e0, e1);
            }
            {
                const float2 f  = *(const float2*)(f2bB + o2);
                const float2 xv = *(const float2*)(xbB + ox);
                const float e0 = f.x * xv.x;
                const float e1 = fl ? f.y * x0B : f.x * xv.y;
                f3r[1][m] = e0; f3r[1][m + 1] = e1;
                *(float2*)(&f3r[1][F3S + m]) = make_float2(e0, e1);
                *(float2*)(oB + 153 + m) = make_float2(e0, e1);
            }
        }
        if (t == 0) {            // f3[0] = f2[0] * x0
            float v = f2r[0][0] * x0A;
            f3r[0][0] = v; f3r[0][F3S] = v; oA[153] = v;
            v = f2r[1][0] * x0B;
            f3r[1][0] = v; f3r[1][F3S] = v; oB[153] = v;
        }
        if (t == 1) {            // f3[815] = f2[135] * x[15]
            float v = f2r[0][135] * xr[0][15];
            f3r[0][815] = v; f3r[0][F3S + 815] = v; oA[153 + 815] = v;
            v = f2r[1][135] * xr[1][15];
            f3r[1][815] = v; f3r[1][F3S + 815] = v; oB[153 + 815] = v;
        }
    }
    __syncthreads();

    // --- order 4: one table word -> two rows; one-ahead table prefetch ------
    const char* __restrict__ f3bA = (const char*)&f3r[0][0];
    const char* __restrict__ f3bB = (const char*)&f3r[1][0];
    float* __restrict__ o4A = oA + 969;
    float* __restrict__ o4B = oB + 969;
    const int a4 = (int)((gA + 969) & 3);
    const int h  = (4 - a4) & 3;

    if (t < h) {
        const uint16_t p = c_t4.v[t];
        o4A[t] = f3r[0][p >> 4] * xr[0][p & 15];
        o4B[t] = f3r[1][p >> 4] * xr[1][p & 15];
    }

    const int nv = (N4 - h) >> 2;
    const uint2* __restrict__ gt = (const uint2*)&c_g4.v[h][0];
    float4* __restrict__ ovA = (float4*)(o4A + h);
    float4* __restrict__ ovB = (float4*)(o4B + h);

    if (t < nv) {
        uint2 w = gt[t];                         // prefetch iteration 0
        #pragma unroll 1
        for (int g = t; g < nv; g += NTHREADS) {
            const int gn = g + NTHREADS;
            const uint2 wn = (gn < nv) ? gt[gn] : w;   // prefetch next
            {
                const float2 r0 = pairv(w.x, f3bA, xbA, x0A);
                const float2 r1 = pairv(w.y, f3bA, xbA, x0A);
                ovA[g] = make_float4(r0.x, r0.y, r1.x, r1.y);
            }
            {
                const float2 r0 = pairv(w.x, f3bB, xbB, x0B);
                const float2 r1 = pairv(w.y, f3bB, xbB, x0B);
                ovB[g] = make_float4(r0.x, r0.y, r1.x, r1.y);
            }
            w = wn;
        }
    }

    const int done = h + 4 * nv;
    if (t < N4 - done) {
        const int m = done + t;
        const uint16_t p = c_t4.v[m];
        o4A[m] = f3r[0][p >> 4] * xr[0][p & 15];
        o4B[m] = f3r[1][p >> 4] * xr[1][p & 15];
    }
}

extern "C" void kernel_launch(void* const* d_in, const int* in_sizes, int n_in,
                              void* d_out, int out_size) {
    const float* in = (const float*)d_in[0];
    float* out = (float*)d_out;
    const int rows = in_sizes[0] / D;            // 8192
    const int half = rows >> 1;                  // 4096, % 4 == 0
    Moment_2774548873409_kernel<<<half, NTHREADS>>>(in, out, half);
}

// round 15
// speedup vs baseline: 1.5477x; 1.0582x over previous
#include <cuda_runtime.h>
#include <cstdint>

// Moment feature expansion, order 4, latent dim 16.
// out[b,t,:] = [1, x(16), f2(136), f3(816), f4(3876)] -> 4845 channels.
// Round 15: R14 (two phase-matched rows/block, pairwise order-3/4, uint2
// tables, f4 one-ahead table prefetch) + order-3 one-ahead table prefetch
// + __stcs streaming-store hints on bulk stores (output is write-once,
// never re-read -> evict-first keeps L2 pressure down).

#define D    16
#define N2   136
#define N3   816
#define N4   3876
#define NOUT 4845
#define NTHREADS 256

#define F2S 137      // floats per f2 copy; copy1 base 548 B == 4 (mod 8)
#define F3S 817      // floats per f3 copy; copy1 base 3268 B == 4 (mod 8)
#define XS  17       // floats per x  copy; copy1 base 68 B == 4 (mod 8)
#define MAXG 969     // max float4 groups in f4 (phase 0)

struct Tab2 { uint16_t v[N2]; };
struct Tab4 { uint16_t v[N4]; };
struct Tp3  { uint32_t v[2][408]; };        // [row-parity phase][pair]
struct Grp4 { uint32_t v[4][MAXG * 2]; };   // [gmem phase][group*2 + pair]

constexpr Tab2 gen2() {
    Tab2 t{}; int m = 0;
    for (int k = 0; k < D; k++)
        for (int j = 0; j <= k; j++)
            t.v[m++] = (uint16_t)((k << 4) | j);
    return t;
}

constexpr Tab4 gen4() {
    Tab4 t{}; int m = 0;
    int off[D] = {};
    for (int j = 0; j < D; j++) {
        int a = D + 2 - j;                       // 18 - j
        off[j] = N3 - a * (a - 1) * (a - 2) / 6;
    }
    for (int k = 0; k < N3; k++)
        for (int j = 0; j < D; j++)
            if (k >= off[j]) t.v[m++] = (uint16_t)((k << 4) | j);
    return t;
}

// Order-3 pair word: [10:0]=f2 byte off (incl parity copy), [11]=reset flag,
// [31:24]=x byte off (incl parity copy).
constexpr Tp3 genP3() {
    Tp3 t{};
    int off[D] = {};
    for (int j = 0; j < D; j++)
        off[j] = N2 - (D - j) * (D - j + 1) / 2;
    uint16_t kk[N3] = {}, jj[N3] = {};
    int m = 0;
    for (int k = 0; k < N2; k++)
        for (int j = 0; j < D; j++)
            if (k >= off[j]) { kk[m] = (uint16_t)k; jj[m] = (uint16_t)j; m++; }
    for (int h = 0; h < 2; h++) {
        int np = (N3 - h) / 2;                   // 408 or 407
        for (int p = 0; p < np; p++) {
            int a = h + 2 * p, b = a + 1;
            uint32_t k2 = kk[a], j = jj[a];
            uint32_t o2 = (k2 & 1u) * (F2S * 4u) + 4u * k2;
            uint32_t ox = (j & 1u) * (XS * 4u) + 4u * j;
            uint32_t fl = (kk[b] != k2) ? 1u : 0u;   // reset <=> !(j->j+1)
            t.v[h][p] = o2 | (fl << 11) | (ox << 24);
        }
    }
    return t;
}

// Order-4 pair word: [12:0]=f3 byte off (incl parity copy), [13]=reset flag,
// [31:24]=x byte off (incl parity copy).
constexpr Grp4 genG() {
    Grp4 t{};
    int off[D] = {};
    for (int j = 0; j < D; j++) {
        int a = D + 2 - j;
        off[j] = N3 - a * (a - 1) * (a - 2) / 6;
    }
    uint16_t kk[N4] = {}, jj[N4] = {};
    int m = 0;
    for (int k = 0; k < N3; k++)
        for (int j = 0; j < D; j++)
            if (k >= off[j]) { kk[m] = (uint16_t)k; jj[m] = (uint16_t)j; m++; }
    for (int h = 0; h < 4; h++) {
        int nv = (N4 - h) >> 2;
        for (int g = 0; g < nv; g++)
            for (int pr = 0; pr < 2; pr++) {
                int a = h + 4 * g + 2 * pr, b = a + 1;
                uint32_t ka = kk[a], ja = jj[a];
                uint32_t o3 = (ka & 1u) * (F3S * 4u) + 4u * ka;   // 8B aligned
                uint32_t ox = (ja & 1u) * (XS * 4u) + 4u * ja;    // 8B aligned
                uint32_t fl = (kk[b] != ka) ? 1u : 0u;
                t.v[h][2 * g + pr] = o3 | (fl << 13) | (ox << 24);
            }
    }
    return t;
}

__device__ constexpr Tab2 c_t2 = gen2();
__device__ constexpr Tab4 c_t4 = gen4();
__device__ __align__(8)  constexpr Tp3  c_p3 = genP3();
__device__ __align__(16) constexpr Grp4 c_g4 = genG();

// One f4 pair: e0 = f3[k]*x[j]; e1 = reset? f3[k+1]*x0 : f3[k]*x[j+1]
__device__ __forceinline__ float2 pairv(uint32_t u,
                                        const char* __restrict__ f3b,
                                        const char* __restrict__ xb,
                                        float x0) {
    const float2 f  = *(const float2*)(f3b + (u & 0x1FFFu));
    const float2 xv = *(const float2*)(xb + (u >> 24));
    return make_float2(f.x * xv.x,
                       (u & (1u << 13)) ? f.y * x0 : f.x * xv.y);
}

__global__ __launch_bounds__(NTHREADS)
void Moment_2774548873409_kernel(const float* __restrict__ in,
                                 float* __restrict__ out,
                                 int half) {
    __shared__ __align__(16) float f3r[2][2 * F3S];
    __shared__ __align__(16) float f2r[2][2 * F2S];
    __shared__ __align__(16) float xr[2][2 * XS];

    const int t = threadIdx.x;
    const int rowA = blockIdx.x;
    const int rowB = rowA + half;       // half % 4 == 0 -> same phases

    const size_t gA = (size_t)rowA * NOUT;
    const size_t gB = (size_t)rowB * NOUT;
    float* __restrict__ oA = out + gA;
    float* __restrict__ oB = out + gB;

    // --- orders 0, 1 (+ pad init), both rows ---
    if (t < D) {
        const float vA = in[(size_t)rowA * D + t];
        xr[0][t] = vA; xr[0][XS + t] = vA; oA[1 + t] = vA;
        const float vB = in[(size_t)rowB * D + t];
        xr[1][t] = vB; xr[1][XS + t] = vB; oB[1 + t] = vB;
    }
    if (t == 0) {
        oA[0] = 1.0f; oB[0] = 1.0f;
        #pragma unroll
        for (int r = 0; r < 2; r++) {
            xr[r][D] = 0.0f;   xr[r][XS + D] = 0.0f;
            f2r[r][N2] = 0.0f; f2r[r][F2S + N2] = 0.0f;
            f3r[r][N3] = 0.0f; f3r[r][F3S + N3] = 0.0f;
        }
    }
    __syncthreads();
    const float x0A = xr[0][0];
    const float x0B = xr[1][0];

    // --- order 2, both rows: 272 work items, strided ---
    #pragma unroll
    for (int it = t; it < 2 * N2; it += NTHREADS) {
        const int r = (it >= N2) ? 1 : 0;
        const int i = it - r * N2;
        const uint16_t p = c_t2.v[i];
        const float v = xr[r][p >> 4] * xr[r][p & 15];
        f2r[r][i] = v; f2r[r][F2S + i] = v;
        (r ? oB : oA)[17 + i] = v;
    }
    __syncthreads();

    const char* __restrict__ f2bA = (const char*)&f2r[0][0];
    const char* __restrict__ f2bB = (const char*)&f2r[1][0];
    const char* __restrict__ xbA  = (const char*)&xr[0][0];
    const char* __restrict__ xbB  = (const char*)&xr[1][0];

    // --- order 3: decode once, apply to both rows; one-ahead prefetch ---
    const int h3 = (int)((gA + 153) & 1);
    if (h3 == 0) {
        if (t < 408) {
            uint32_t w = c_p3.v[0][t];
            #pragma unroll 1
            for (int p = t; p < 408; p += NTHREADS) {
                const int pn = p + NTHREADS;
                const uint32_t wn = (pn < 408) ? c_p3.v[0][pn] : w;
                const uint32_t o2 = w & 0x7FFu;
                const uint32_t ox = w >> 24;
                const uint32_t fl = w & (1u << 11);
                const int m = 2 * p;
                {
                    const float2 f  = *(const float2*)(f2bA + o2);
                    const float2 xv = *(const float2*)(xbA + ox);
                    const float e0 = f.x * xv.x;
                    const float e1 = fl ? f.y * x0A : f.x * xv.y;
                    *(float2*)(&f3r[0][m]) = make_float2(e0, e1);
                    f3r[0][F3S + m] = e0; f3r[0][F3S + m + 1] = e1;
                    __stcs((float2*)(oA + 153 + m), make_float2(e0, e1));
                }
                {
                    const float2 f  = *(const float2*)(f2bB + o2);
                    const float2 xv = *(const float2*)(xbB + ox);
                    const float e0 = f.x * xv.x;
                    const float e1 = fl ? f.y * x0B : f.x * xv.y;
                    *(float2*)(&f3r[1][m]) = make_float2(e0, e1);
                    f3r[1][F3S + m] = e0; f3r[1][F3S + m + 1] = e1;
                    __stcs((float2*)(oB + 153 + m), make_float2(e0, e1));
                }
                w = wn;
            }
        }
    } else {
        if (t < 407) {
            uint32_t w = c_p3.v[1][t];
            #pragma unroll 1
            for (int p = t; p < 407; p += NTHREADS) {
                const int pn = p + NTHREADS;
                const uint32_t wn = (pn < 407) ? c_p3.v[1][pn] : w;
                const uint32_t o2 = w & 0x7FFu;
                const uint32_t ox = w >> 24;
                const uint32_t fl = w & (1u << 11);
                const int m = 1 + 2 * p;
                {
                    const float2 f  = *(const float2*)(f2bA + o2);
                    const float2 xv = *(const float2*)(xbA + ox);
                    const float e0 = f.x * xv.x;
                    const float e1 = fl ? f.y * x0A : f.x * xv.y;
                    f3r[0][m] = e0; f3r[0][m + 1] = e1;
                    *(float2*)(&f3r[0][F3S + m]) = make_float2(e0, e1);
                    __stcs((float2*)(oA + 153 + m), make_float2(e0, e1));
                }
                {
                    const float2 f  = *(const float2*)(f2bB + o2);
                    const float2 xv = *(const float2*)(xbB + ox);
                    const float e0 = f.x * xv.x;
                    const float e1 = fl ? f.y * x0B : f.x * xv.y;
                    f3r[1][m] = e0; f3r[1][m + 1] = e1;
                    *(float2*)(&f3r[1][F3S + m]) = make_float2(e0, e1);
                    __stcs((float2*)(oB + 153 + m), make_float2(e0, e1));
                }
                w = wn;
            }
        }
        if (t == 0) {            // f3[0] = f2[0] * x0
            float v = f2r[0][0] * x0A;
            f3r[0][0] = v; f3r[0][F3S] = v; oA[153] = v;
            v = f2r[1][0] * x0B;
            f3r[1][0] = v; f3r[1][F3S] = v; oB[153] = v;
        }
        if (t == 1) {            // f3[815] = f2[135] * x[15]
            float v = f2r[0][135] * xr[0][15];
            f3r[0][815] = v; f3r[0][F3S + 815] = v; oA[153 + 815] = v;
            v = f2r[1][135] * xr[1][15];
            f3r[1][815] = v; f3r[1][F3S + 815] = v; oB[153 + 815] = v;
        }
    }
    __syncthreads();

    // --- order 4: one table word -> two rows; one-ahead table prefetch ------
    const char* __restrict__ f3bA = (const char*)&f3r[0][0];
    const char* __restrict__ f3bB = (const char*)&f3r[1][0];
    float* __restrict__ o4A = oA + 969;
    float* __restrict__ o4B = oB + 969;
    const int a4 = (int)((gA + 969) & 3);
    const int h  = (4 - a4) & 3;

    if (t < h) {
        const uint16_t p = c_t4.v[t];
        o4A[t] = f3r[0][p >> 4] * xr[0][p & 15];
        o4B[t] = f3r[1][p >> 4] * xr[1][p & 15];
    }

    const int nv = (N4 - h) >> 2;
    const uint2* __restrict__ gt = (const uint2*)&c_g4.v[h][0];
    float4* __restrict__ ovA = (float4*)(o4A + h);
    float4* __restrict__ ovB = (float4*)(o4B + h);

    if (t < nv) {
        uint2 w = gt[t];                         // prefetch iteration 0
        #pragma unroll 1
        for (int g = t; g < nv; g += NTHREADS) {
            const int gn = g + NTHREADS;
            const uint2 wn = (gn < nv) ? gt[gn] : w;   // prefetch next
            {
                const float2 r0 = pairv(w.x, f3bA, xbA, x0A);
                const float2 r1 = pairv(w.y, f3bA, xbA, x0A);
                __stcs(ovA + g, make_float4(r0.x, r0.y, r1.x, r1.y));
            }
            {
                const float2 r0 = pairv(w.x, f3bB, xbB, x0B);
                const float2 r1 = pairv(w.y, f3bB, xbB, x0B);
                __stcs(ovB + g, make_float4(r0.x, r0.y, r1.x, r1.y));
            }
            w = wn;
        }
    }

    const int done = h + 4 * nv;
    if (t < N4 - done) {
        const int m = done + t;
        const uint16_t p = c_t4.v[m];
        o4A[m] = f3r[0][p >> 4] * xr[0][p & 15];
        o4B[m] = f3r[1][p >> 4] * xr[1][p & 15];
    }
}

extern "C" void kernel_launch(void* const* d_in, const int* in_sizes, int n_in,
                              void* d_out, int out_size) {
    const float* in = (const float*)d_in[0];
    float* out = (float*)d_out;
    const int rows = in_sizes[0] / D;            // 8192
    const int half = rows >> 1;                  // 4096, % 4 == 0
    Moment_2774548873409_kernel<<<half, NTHREADS>>>(in, out, half);
}

// round 16
// speedup vs baseline: 1.5719x; 1.0156x over previous
#include <cuda_runtime.h>
#include <cstdint>

// Moment feature expansion, order 4, latent dim 16.
// out[b,t,:] = [1, x(16), f2(136), f3(816), f4(3876)] -> 4845 channels.
// Round 16: R15 + 128B-aligned f4 store windows: skip c in [0,8) leading
// float4 groups per row so every warp STG.128 window covers exactly 4 cache
// lines (was 5). rowB=rowA+4096 shares the same c (4096*19380 % 128 == 0).
// Skipped groups fold into the scalar head (<=31 elems via element table).

#define D    16
#define N2   136
#define N3   816
#define N4   3876
#define NOUT 4845
#define NTHREADS 256

#define F2S 137      // floats per f2 copy; copy1 base 548 B == 4 (mod 8)
#define F3S 817      // floats per f3 copy; copy1 base 3268 B == 4 (mod 8)
#define XS  17       // floats per x  copy; copy1 base 68 B == 4 (mod 8)
#define MAXG 969     // max float4 groups in f4 (phase 0)

struct Tab2 { uint16_t v[N2]; };
struct Tab4 { uint16_t v[N4]; };
struct Tp3  { uint32_t v[2][408]; };        // [row-parity phase][pair]
struct Grp4 { uint32_t v[4][MAXG * 2]; };   // [gmem phase][group*2 + pair]

constexpr Tab2 gen2() {
    Tab2 t{}; int m = 0;
    for (int k = 0; k < D; k++)
        for (int j = 0; j <= k; j++)
            t.v[m++] = (uint16_t)((k << 4) | j);
    return t;
}

constexpr Tab4 gen4() {
    Tab4 t{}; int m = 0;
    int off[D] = {};
    for (int j = 0; j < D; j++) {
        int a = D + 2 - j;                       // 18 - j
        off[j] = N3 - a * (a - 1) * (a - 2) / 6;
    }
    for (int k = 0; k < N3; k++)
        for (int j = 0; j < D; j++)
            if (k >= off[j]) t.v[m++] = (uint16_t)((k << 4) | j);
    return t;
}

// Order-3 pair word: [10:0]=f2 byte off (incl parity copy), [11]=reset flag,
// [31:24]=x byte off (incl parity copy).
constexpr Tp3 genP3() {
    Tp3 t{};
    int off[D] = {};
    for (int j = 0; j < D; j++)
        off[j] = N2 - (D - j) * (D - j + 1) / 2;
    uint16_t kk[N3] = {}, jj[N3] = {};
    int m = 0;
    for (int k = 0; k < N2; k++)
        for (int j = 0; j < D; j++)
            if (k >= off[j]) { kk[m] = (uint16_t)k; jj[m] = (uint16_t)j; m++; }
    for (int h = 0; h < 2; h++) {
        int np = (N3 - h) / 2;                   // 408 or 407
        for (int p = 0; p < np; p++) {
            int a = h + 2 * p, b = a + 1;
            uint32_t k2 = kk[a], j = jj[a];
            uint32_t o2 = (k2 & 1u) * (F2S * 4u) + 4u * k2;
            uint32_t ox = (j & 1u) * (XS * 4u) + 4u * j;
            uint32_t fl = (kk[b] != k2) ? 1u : 0u;   // reset <=> !(j->j+1)
            t.v[h][p] = o2 | (fl << 11) | (ox << 24);
        }
    }
    return t;
}

// Order-4 pair word: [12:0]=f3 byte off (incl parity copy), [13]=reset flag,
// [31:24]=x byte off (incl parity copy).
constexpr Grp4 genG() {
    Grp4 t{};
    int off[D] = {};
    for (int j = 0; j < D; j++) {
        int a = D + 2 - j;
        off[j] = N3 - a * (a - 1) * (a - 2) / 6;
    }
    uint16_t kk[N4] = {}, jj[N4] = {};
    int m = 0;
    for (int k = 0; k < N3; k++)
        for (int j = 0; j < D; j++)
            if (k >= off[j]) { kk[m] = (uint16_t)k; jj[m] = (uint16_t)j; m++; }
    for (int h = 0; h < 4; h++) {
        int nv = (N4 - h) >> 2;
        for (int g = 0; g < nv; g++)
            for (int pr = 0; pr < 2; pr++) {
                int a = h + 4 * g + 2 * pr, b = a + 1;
                uint32_t ka = kk[a], ja = jj[a];
                uint32_t o3 = (ka & 1u) * (F3S * 4u) + 4u * ka;   // 8B aligned
                uint32_t ox = (ja & 1u) * (XS * 4u) + 4u * ja;    // 8B aligned
                uint32_t fl = (kk[b] != ka) ? 1u : 0u;
                t.v[h][2 * g + pr] = o3 | (fl << 13) | (ox << 24);
            }
    }
    return t;
}

__device__ constexpr Tab2 c_t2 = gen2();
__device__ constexpr Tab4 c_t4 = gen4();
__device__ __align__(8)  constexpr Tp3  c_p3 = genP3();
__device__ __align__(16) constexpr Grp4 c_g4 = genG();

// One f4 pair: e0 = f3[k]*x[j]; e1 = reset? f3[k+1]*x0 : f3[k]*x[j+1]
__device__ __forceinline__ float2 pairv(uint32_t u,
                                        const char* __restrict__ f3b,
                                        const char* __restrict__ xb,
                                        float x0) {
    const float2 f  = *(const float2*)(f3b + (u & 0x1FFFu));
    const float2 xv = *(const float2*)(xb + (u >> 24));
    return make_float2(f.x * xv.x,
                       (u & (1u << 13)) ? f.y * x0 : f.x * xv.y);
}

__global__ __launch_bounds__(NTHREADS)
void Moment_2774548873409_kernel(const float* __restrict__ in,
                                 float* __restrict__ out,
                                 int half) {
    __shared__ __align__(16) float f3r[2][2 * F3S];
    __shared__ __align__(16) float f2r[2][2 * F2S];
    __shared__ __align__(16) float xr[2][2 * XS];

    const int t = threadIdx.x;
    const int rowA = blockIdx.x;
    const int rowB = rowA + half;       // half % 4 == 0 -> same phases

    const size_t gA = (size_t)rowA * NOUT;
    const size_t gB = (size_t)rowB * NOUT;
    float* __restrict__ oA = out + gA;
    float* __restrict__ oB = out + gB;

    // --- orders 0, 1 (+ pad init), both rows ---
    if (t < D) {
        const float vA = in[(size_t)rowA * D + t];
        xr[0][t] = vA; xr[0][XS + t] = vA; oA[1 + t] = vA;
        const float vB = in[(size_t)rowB * D + t];
        xr[1][t] = vB; xr[1][XS + t] = vB; oB[1 + t] = vB;
    }
    if (t == 0) {
        oA[0] = 1.0f; oB[0] = 1.0f;
        #pragma unroll
        for (int r = 0; r < 2; r++) {
            xr[r][D] = 0.0f;   xr[r][XS + D] = 0.0f;
            f2r[r][N2] = 0.0f; f2r[r][F2S + N2] = 0.0f;
            f3r[r][N3] = 0.0f; f3r[r][F3S + N3] = 0.0f;
        }
    }
    __syncthreads();
    const float x0A = xr[0][0];
    const float x0B = xr[1][0];

    // --- order 2, both rows: 272 work items, strided ---
    #pragma unroll
    for (int it = t; it < 2 * N2; it += NTHREADS) {
        const int r = (it >= N2) ? 1 : 0;
        const int i = it - r * N2;
        const uint16_t p = c_t2.v[i];
        const float v = xr[r][p >> 4] * xr[r][p & 15];
        f2r[r][i] = v; f2r[r][F2S + i] = v;
        (r ? oB : oA)[17 + i] = v;
    }
    __syncthreads();

    const char* __restrict__ f2bA = (const char*)&f2r[0][0];
    const char* __restrict__ f2bB = (const char*)&f2r[1][0];
    const char* __restrict__ xbA  = (const char*)&xr[0][0];
    const char* __restrict__ xbB  = (const char*)&xr[1][0];

    // --- order 3: decode once, apply to both rows; one-ahead prefetch ---
    const int h3 = (int)((gA + 153) & 1);
    if (h3 == 0) {
        if (t < 408) {
            uint32_t w = c_p3.v[0][t];
            #pragma unroll 1
            for (int p = t; p < 408; p += NTHREADS) {
                const int pn = p + NTHREADS;
                const uint32_t wn = (pn < 408) ? c_p3.v[0][pn] : w;
                const uint32_t o2 = w & 0x7FFu;
                const uint32_t ox = w >> 24;
                const uint32_t fl = w & (1u << 11);
                const int m = 2 * p;
                {
                    const float2 f  = *(const float2*)(f2bA + o2);
                    const float2 xv = *(const float2*)(xbA + ox);
                    const float e0 = f.x * xv.x;
                    const float e1 = fl ? f.y * x0A : f.x * xv.y;
                    *(float2*)(&f3r[0][m]) = make_float2(e0, e1);
                    f3r[0][F3S + m] = e0; f3r[0][F3S + m + 1] = e1;
                    __stcs((float2*)(oA + 153 + m), make_float2(e0, e1));
                }
                {
                    const float2 f  = *(const float2*)(f2bB + o2);
                    const float2 xv = *(const float2*)(xbB + ox);
                    const float e0 = f.x * xv.x;
                    const float e1 = fl ? f.y * x0B : f.x * xv.y;
                    *(float2*)(&f3r[1][m]) = make_float2(e0, e1);
                    f3r[1][F3S + m] = e0; f3r[1][F3S + m + 1] = e1;
                    __stcs((float2*)(oB + 153 + m), make_float2(e0, e1));
                }
                w = wn;
            }
        }
    } else {
        if (t < 407) {
            uint32_t w = c_p3.v[1][t];
            #pragma unroll 1
            for (int p = t; p < 407; p += NTHREADS) {
                const int pn = p + NTHREADS;
                const uint32_t wn = (pn < 407) ? c_p3.v[1][pn] : w;
                const uint32_t o2 = w & 0x7FFu;
                const uint32_t ox = w >> 24;
                const uint32_t fl = w & (1u << 11);
                const int m = 1 + 2 * p;
                {
                    const float2 f  = *(const float2*)(f2bA + o2);
                    const float2 xv = *(const float2*)(xbA + ox);
                    const float e0 = f.x * xv.x;
                    const float e1 = fl ? f.y * x0A : f.x * xv.y;
                    f3r[0][m] = e0; f3r[0][m + 1] = e1;
                    *(float2*)(&f3r[0][F3S + m]) = make_float2(e0, e1);
                    __stcs((float2*)(oA + 153 + m), make_float2(e0, e1));
                }
                {
                    const float2 f  = *(const float2*)(f2bB + o2);
                    const float2 xv = *(const float2*)(xbB + ox);
                    const float e0 = f.x * xv.x;
                    const float e1 = fl ? f.y * x0B : f.x * xv.y;
                    f3r[1][m] = e0; f3r[1][m + 1] = e1;
                    *(float2*)(&f3r[1][F3S + m]) = make_float2(e0, e1);
                    __stcs((float2*)(oB + 153 + m), make_float2(e0, e1));
                }
                w = wn;
            }
        }
        if (t == 0) {            // f3[0] = f2[0] * x0
            float v = f2r[0][0] * x0A;
            f3r[0][0] = v; f3r[0][F3S] = v; oA[153] = v;
            v = f2r[1][0] * x0B;
            f3r[1][0] = v; f3r[1][F3S] = v; oB[153] = v;
        }
        if (t == 1) {            // f3[815] = f2[135] * x[15]
            float v = f2r[0][135] * xr[0][15];
            f3r[0][815] = v; f3r[0][F3S + 815] = v; oA[153 + 815] = v;
            v = f2r[1][135] * xr[1][15];
            f3r[1][815] = v; f3r[1][F3S + 815] = v; oB[153 + 815] = v;
        }
    }
    __syncthreads();

    // --- order 4: prefetched pairwise loop, 128B-aligned store windows -----
    const char* __restrict__ f3bA = (const char*)&f3r[0][0];
    const char* __restrict__ f3bB = (const char*)&f3r[1][0];
    float* __restrict__ o4A = oA + 969;
    float* __restrict__ o4B = oB + 969;
    const int a4 = (int)((gA + 969) & 3);
    const int h  = (4 - a4) & 3;

    const int nv = (N4 - h) >> 2;
    float4* __restrict__ ovA = (float4*)(o4A + h);
    float4* __restrict__ ovB = (float4*)(o4B + h);

    // Groups to skip so ovA+c is 128B-aligned (rowB shares the same phase:
    // row stride * half is a multiple of 128 bytes).
    const int c = (int)(((0u - (uint32_t)(uintptr_t)ovA) & 127u) >> 4); // 0..7

    // Scalar head: elements m in [0, h + 4c)  (at most 3 + 28 = 31).
    const int headN = h + 4 * c;
    if (t < headN) {
        const uint16_t p = c_t4.v[t];
        __stcs(o4A + t, f3r[0][p >> 4] * xr[0][p & 15]);
        __stcs(o4B + t, f3r[1][p >> 4] * xr[1][p & 15]);
    }

    const uint2* __restrict__ gt = (const uint2*)&c_g4.v[h][0];
    const int g0 = c + t;
    if (g0 < nv) {
        uint2 w = gt[g0];                        // prefetch first iteration
        #pragma unroll 1
        for (int g = g0; g < nv; g += NTHREADS) {
            const int gn = g + NTHREADS;
            const uint2 wn = (gn < nv) ? gt[gn] : w;   // prefetch next
            {
                const float2 r0 = pairv(w.x, f3bA, xbA, x0A);
                const float2 r1 = pairv(w.y, f3bA, xbA, x0A);
                __stcs(ovA + g, make_float4(r0.x, r0.y, r1.x, r1.y));
            }
            {
                const float2 r0 = pairv(w.x, f3bB, xbB, x0B);
                const float2 r1 = pairv(w.y, f3bB, xbB, x0B);
                __stcs(ovB + g, make_float4(r0.x, r0.y, r1.x, r1.y));
            }
            w = wn;
        }
    }

    const int done = h + 4 * nv;
    if (t < N4 - done) {
        const int m = done + t;
        const uint16_t p = c_t4.v[m];
        __stcs(o4A + m, f3r[0][p >> 4] * xr[0][p & 15]);
        __stcs(o4B + m, f3r[1][p >> 4] * xr[1][p & 15]);
    }
}

extern "C" void kernel_launch(void* const* d_in, const int* in_sizes, int n_in,
                              void* d_out, int out_size) {
    const float* in = (const float*)d_in[0];
    float* out = (float*)d_out;
    const int rows = in_sizes[0] / D;            // 8192
    const int half = rows >> 1;                  // 4096, % 4 == 0
    Moment_2774548873409_kernel<<<half, NTHREADS>>>(in, out, half);
}